// round 2
// baseline (speedup 1.0000x reference)
#include <cuda_runtime.h>
#include <cstdint>

// Problem dims (fixed for this problem instance)
#define Bb 32
#define Cc 256
#define Hh 36
#define Ww 64
#define Nn 4096
#define Kk (Hh * Ww)   // 2304

// Scratch: Gaussian masks, tf32-rounded fp32, [n, HW] row-major. 37.75 MB.
__device__ float g_G[(size_t)Nn * Kk];

__device__ __forceinline__ uint32_t f32_to_tf32(float x) {
    uint32_t u;
    asm("cvt.rna.tf32.f32 %0, %1;" : "=r"(u) : "f"(x));
    return u;
}

__device__ __forceinline__ void mma_tf32(float d[4], const uint32_t a[4], const uint32_t b[2]) {
    asm volatile(
        "mma.sync.aligned.m16n8k8.row.col.f32.tf32.tf32.f32 "
        "{%0,%1,%2,%3}, {%4,%5,%6,%7}, {%8,%9}, {%0,%1,%2,%3};\n"
        : "+f"(d[0]), "+f"(d[1]), "+f"(d[2]), "+f"(d[3])
        : "r"(a[0]), "r"(a[1]), "r"(a[2]), "r"(a[3]),
          "r"(b[0]), "r"(b[1]));
}

// ---------------------------------------------------------------------------
// Kernel 1: compute G[n, h*W+w] = exp(-A/denom), tf32-rounded.
// ---------------------------------------------------------------------------
__global__ void gauss_kernel(const float* __restrict__ mu,
                             const float* __restrict__ logsx,
                             const float* __restrict__ logsy,
                             const float* __restrict__ rho) {
    const int n = blockIdx.x;
    const float mux = mu[2 * n];
    const float muy = mu[2 * n + 1];
    const float sx = expf(logsx[n]) + 1e-6f;
    const float sy = expf(logsy[n]) + 1e-6f;
    const float r  = tanhf(rho[n]);
    const float isx = 1.0f / sx;
    const float isy = 1.0f / sy;
    const float iden = 1.0f / (2.0f * (1.0f - r * r + 1e-6f));
    float* Grow = g_G + (size_t)n * Kk;
    for (int k = threadIdx.x; k < Kk; k += blockDim.x) {
        const int h = k / Ww;
        const int w = k - h * Ww;
        const float x = -1.0f + w * (2.0f / (Ww - 1));
        const float y = -1.0f + h * (2.0f / (Hh - 1));
        const float xc = (x - mux) * isx;
        const float yc = (y - muy) * isy;
        const float A = xc * xc + yc * yc - 2.0f * r * xc * yc;
        Grow[k] = __uint_as_float(f32_to_tf32(expf(-A * iden)));
    }
}

// ---------------------------------------------------------------------------
// Kernel 2: per-batch GEMM pooled = G (n x K) * feat[b]^T (K x C), tf32 MMA,
// fused epilogue out[b,n] += sum_c pooled[n,c] * weight[n,c].
// ---------------------------------------------------------------------------
#define BM 128
#define BN 128
#define BK 16
#define AST (BK + 4)    // 20 floats  -> conflict-free A LDS
#define BST (BN + 8)    // 136 floats

// XOR swizzle on B columns: keeps both STS (k varies per lane) and LDS
// (t4 varies per lane) conflict-free with BST=136.
__device__ __forceinline__ int bswz(int k, int c) {
    return c ^ (((k >> 2) & 3) << 3);
}

__global__ __launch_bounds__(256)
void gemm_kernel(const float* __restrict__ feat,
                 const float* __restrict__ weight,
                 float* __restrict__ out) {
    __shared__ float As[2][BM][AST];
    __shared__ float Bs[2][BK][BST];

    const int n0 = blockIdx.x * BM;
    const int c0 = blockIdx.y * BN;
    const int b  = blockIdx.z;

    const int t    = threadIdx.x;
    const int lane = t & 31;
    const int wid  = t >> 5;
    const int g    = lane >> 2;   // groupID
    const int t4   = lane & 3;    // threadID_in_group
    const int wm   = wid & 1;     // warp m index (0..1): 64 rows each
    const int wn   = wid >> 1;    // warp n index (0..3): 32 cols each

    const int lr = t >> 2;        // 0..63  (row for gmem loads)
    const int lk = (t & 3) << 2;  // 0,4,8,12

    const float* gA0 = g_G + (size_t)(n0 + lr) * Kk + lk;
    const float* gA1 = g_G + (size_t)(n0 + lr + 64) * Kk + lk;
    const float* gB0 = feat + ((size_t)b * Cc + c0 + lr) * Kk + lk;
    const float* gB1 = feat + ((size_t)b * Cc + c0 + lr + 64) * Kk + lk;

    float acc[4][4][4];
    #pragma unroll
    for (int i = 0; i < 4; i++)
        #pragma unroll
        for (int j = 0; j < 4; j++)
            #pragma unroll
            for (int q = 0; q < 4; q++) acc[i][j][q] = 0.0f;

    float4 ra0 = *(const float4*)(gA0);
    float4 ra1 = *(const float4*)(gA1);
    float4 rb0 = *(const float4*)(gB0);
    float4 rb1 = *(const float4*)(gB1);

    // stage tile 0 into buffer 0 (feat tf32-rounded on the fly)
    *(float4*)&As[0][lr][lk]      = ra0;
    *(float4*)&As[0][lr + 64][lk] = ra1;
    Bs[0][lk + 0][bswz(lk + 0, lr)] = __uint_as_float(f32_to_tf32(rb0.x));
    Bs[0][lk + 1][bswz(lk + 1, lr)] = __uint_as_float(f32_to_tf32(rb0.y));
    Bs[0][lk + 2][bswz(lk + 2, lr)] = __uint_as_float(f32_to_tf32(rb0.z));
    Bs[0][lk + 3][bswz(lk + 3, lr)] = __uint_as_float(f32_to_tf32(rb0.w));
    Bs[0][lk + 0][bswz(lk + 0, lr + 64)] = __uint_as_float(f32_to_tf32(rb1.x));
    Bs[0][lk + 1][bswz(lk + 1, lr + 64)] = __uint_as_float(f32_to_tf32(rb1.y));
    Bs[0][lk + 2][bswz(lk + 2, lr + 64)] = __uint_as_float(f32_to_tf32(rb1.z));
    Bs[0][lk + 3][bswz(lk + 3, lr + 64)] = __uint_as_float(f32_to_tf32(rb1.w));
    __syncthreads();

    int buf = 0;
    #pragma unroll 1
    for (int k0 = 0; k0 < Kk; k0 += BK) {
        const bool has_next = (k0 + BK) < Kk;
        if (has_next) {
            ra0 = *(const float4*)(gA0 + k0 + BK);
            ra1 = *(const float4*)(gA1 + k0 + BK);
            rb0 = *(const float4*)(gB0 + k0 + BK);
            rb1 = *(const float4*)(gB1 + k0 + BK);
        }
        #pragma unroll
        for (int kk = 0; kk < BK; kk += 8) {
            uint32_t afr[4][4];
            uint32_t bfr[4][2];
            #pragma unroll
            for (int mf = 0; mf < 4; mf++) {
                const int row = wm * 64 + mf * 16 + g;
                afr[mf][0] = __float_as_uint(As[buf][row][kk + t4]);
                afr[mf][1] = __float_as_uint(As[buf][row + 8][kk + t4]);
                afr[mf][2] = __float_as_uint(As[buf][row][kk + t4 + 4]);
                afr[mf][3] = __float_as_uint(As[buf][row + 8][kk + t4 + 4]);
            }
            #pragma unroll
            for (int nf = 0; nf < 4; nf++) {
                const int col = wn * 32 + nf * 8 + g;
                bfr[nf][0] = __float_as_uint(Bs[buf][kk + t4][bswz(kk + t4, col)]);
                bfr[nf][1] = __float_as_uint(Bs[buf][kk + t4 + 4][bswz(kk + t4 + 4, col)]);
            }
            #pragma unroll
            for (int mf = 0; mf < 4; mf++)
                #pragma unroll
                for (int nf = 0; nf < 4; nf++)
                    mma_tf32(acc[mf][nf], afr[mf], bfr[nf]);
        }
        if (has_next) {
            const int nb = buf ^ 1;
            *(float4*)&As[nb][lr][lk]      = ra0;
            *(float4*)&As[nb][lr + 64][lk] = ra1;
            Bs[nb][lk + 0][bswz(lk + 0, lr)] = __uint_as_float(f32_to_tf32(rb0.x));
            Bs[nb][lk + 1][bswz(lk + 1, lr)] = __uint_as_float(f32_to_tf32(rb0.y));
            Bs[nb][lk + 2][bswz(lk + 2, lr)] = __uint_as_float(f32_to_tf32(rb0.z));
            Bs[nb][lk + 3][bswz(lk + 3, lr)] = __uint_as_float(f32_to_tf32(rb0.w));
            Bs[nb][lk + 0][bswz(lk + 0, lr + 64)] = __uint_as_float(f32_to_tf32(rb1.x));
            Bs[nb][lk + 1][bswz(lk + 1, lr + 64)] = __uint_as_float(f32_to_tf32(rb1.y));
            Bs[nb][lk + 2][bswz(lk + 2, lr + 64)] = __uint_as_float(f32_to_tf32(rb1.z));
            Bs[nb][lk + 3][bswz(lk + 3, lr + 64)] = __uint_as_float(f32_to_tf32(rb1.w));
            __syncthreads();
            buf = nb;
        }
    }

    // Fused epilogue: out[b, n] += sum_c pooled[n, c] * weight[n, c]
    #pragma unroll
    for (int mf = 0; mf < 4; mf++) {
        const int r0 = wm * 64 + mf * 16 + g;
        const int r1 = r0 + 8;
        float p0 = 0.0f, p1 = 0.0f;
        #pragma unroll
        for (int nf = 0; nf < 4; nf++) {
            const int cg = c0 + wn * 32 + nf * 8 + (t4 << 1);
            const float* w0 = weight + (size_t)(n0 + r0) * Cc + cg;
            const float* w1 = weight + (size_t)(n0 + r1) * Cc + cg;
            p0 += acc[mf][nf][0] * w0[0] + acc[mf][nf][1] * w0[1];
            p1 += acc[mf][nf][2] * w1[0] + acc[mf][nf][3] * w1[1];
        }
        p0 += __shfl_xor_sync(0xffffffffu, p0, 1);
        p0 += __shfl_xor_sync(0xffffffffu, p0, 2);
        p1 += __shfl_xor_sync(0xffffffffu, p1, 1);
        p1 += __shfl_xor_sync(0xffffffffu, p1, 2);
        if (t4 == 0) {
            atomicAdd(out + (size_t)b * Nn + n0 + r0, p0);
            atomicAdd(out + (size_t)b * Nn + n0 + r1, p1);
        }
    }
}

// ---------------------------------------------------------------------------
extern "C" void kernel_launch(void* const* d_in, const int* in_sizes, int n_in,
                              void* d_out, int out_size) {
    const float* feat   = (const float*)d_in[0];
    const float* mu     = (const float*)d_in[1];
    const float* logsx  = (const float*)d_in[2];
    const float* logsy  = (const float*)d_in[3];
    const float* rho    = (const float*)d_in[4];
    const float* weight = (const float*)d_in[5];
    float* out = (float*)d_out;

    cudaMemsetAsync(out, 0, (size_t)out_size * sizeof(float));
    gauss_kernel<<<Nn, 256>>>(mu, logsx, logsy, rho);
    dim3 grid(Nn / BM, Cc / BN, Bb);
    gemm_kernel<<<grid, 256>>>(feat, weight, out);
}